// round 10
// baseline (speedup 1.0000x reference)
#include <cuda_runtime.h>
#include <cuda_fp16.h>
#include <cstdint>

#define BB 256
#define NN 2048
#define DD 128
#define RPB 2048
#define SLICES (BB*128)           // 32768 16-row slices
#define GRID_MAIN 296             // 2 persistent CTAs/SM
#define NWARPS (GRID_MAIN*8)      // 2368 warps
#define CHUNK 14                  // ceil(SLICES / NWARPS)
// smem: W16 [0,32768) | per-warp D/E overlay 8 x 8448 [32768,100352)
#define SMEM_MAIN 100352

// ---------------- device scratch ----------------
__device__ float g_acc[BB*DD];
__device__ int   g_histT[BB*BB];   // [seg][batch]
__device__ int   g_perm[BB*RPB];   // packed (node<<8)|seg ; sentinel sign bit
__device__ float g_T[BB*DD];

// ---------------- helpers ----------------
static __device__ __forceinline__ uint32_t smem_u32(const void* p){
  uint32_t a;
  asm("{ .reg .u64 t; cvta.to.shared.u64 t, %1; cvt.u32.u64 %0, t; }" : "=r"(a) : "l"(p));
  return a;
}
static __device__ __forceinline__ uint32_t h2u(__half2 h){
  union { __half2 h; uint32_t u; } c; c.h = h; return c.u;
}
static __device__ __forceinline__ void ldsm4(uint32_t &r0, uint32_t &r1, uint32_t &r2, uint32_t &r3, uint32_t a){
  asm volatile("ldmatrix.sync.aligned.m8n8.x4.shared.b16 {%0,%1,%2,%3}, [%4];"
    : "=r"(r0), "=r"(r1), "=r"(r2), "=r"(r3) : "r"(a));
}
static __device__ __forceinline__ void mma16816(float* c, uint32_t a0, uint32_t a1, uint32_t a2, uint32_t a3,
                                                uint32_t b0, uint32_t b1){
  asm volatile("mma.sync.aligned.m16n8k16.row.col.f32.f16.f16.f32 "
    "{%0,%1,%2,%3}, {%4,%5,%6,%7}, {%8,%9}, {%0,%1,%2,%3};"
    : "+f"(c[0]), "+f"(c[1]), "+f"(c[2]), "+f"(c[3])
    : "r"(a0), "r"(a1), "r"(a2), "r"(a3), "r"(b0), "r"(b1));
}

// ---------------- fused prep: 256 blocks; hist+scan+scatter+prepT per batch ----------------
__global__ void __launch_bounds__(512) k_prep(const int* __restrict__ bidx,
                                              const float* __restrict__ embs,
                                              const float* __restrict__ W1,
                                              const float* __restrict__ b1){
  int b = blockIdx.x, t = threadIdx.x;
  __shared__ int sb[NN];
  __shared__ float tg[DD];
  __shared__ int h[BB];
  __shared__ int wsum[8];

  if (t < BB) h[t] = 0;
  if (t < DD){ g_acc[b*DD + t] = 0.f; tg[t] = embs[(size_t)b*NN*DD + t]; }
  for (int i = t; i < NN-1; i += 512) sb[i] = bidx[b*NN + 1 + i];
  __syncthreads();

  // prepT (independent): d = t>>2, k-quarter = t&3
  {
    int d = t >> 2, kq = t & 3;
    const float* w = W1 + (size_t)d*2*DD + kq*32;
    const float* tgp = tg + kq*32;
    float s = 0.f;
    #pragma unroll
    for (int k = 0; k < 32; k++) s += w[k]*tgp[k];
    s += __shfl_xor_sync(0xffffffffu, s, 1);
    s += __shfl_xor_sync(0xffffffffu, s, 2);
    if (kq == 0) g_T[b*DD + d] = s + b1[d];
  }

  for (int i = t; i < NN-1; i += 512)
    atomicAdd(&h[sb[i]], 1);
  __syncthreads();

  int lane = t & 31, wrp = t >> 5;
  int v = 0, x = 0;
  if (t < BB){ v = h[t]; g_histT[t*BB + b] = v; }
  x = v;
  #pragma unroll
  for (int o = 1; o < 32; o <<= 1){
    int y = __shfl_up_sync(0xffffffffu, x, o);
    if (lane >= o) x += y;
  }
  if (t < BB && lane == 31) wsum[wrp] = x;
  __syncthreads();
  if (t < 32){
    int s = (t < 8) ? wsum[t] : 0;
    #pragma unroll
    for (int o = 1; o < 8; o <<= 1){
      int y = __shfl_up_sync(0xffffffffu, s, o);
      if (t >= o) s += y;
    }
    if (t < 8) wsum[t] = s;
  }
  __syncthreads();
  if (t < BB){
    int off = (wrp > 0) ? wsum[wrp-1] : 0;
    h[t] = off + x - v;
  }
  __syncthreads();
  for (int i = t; i < NN-1; i += 512){
    int s = sb[i];
    int pos = atomicAdd(&h[s], 1);
    g_perm[b*RPB + pos] = ((1 + i) << 8) | s;
  }
  if (t == 0) g_perm[b*RPB + NN-1] = (int)(0x80000000u | (1u << 8));
}

// ---------------- main: warp-autonomous contiguous slice chunks ----------------
__global__ void __launch_bounds__(256, 2) k_main(const float* __restrict__ embs,
                                                 const float* __restrict__ W1){
  extern __shared__ char sm[];
  uint32_t sbase = smem_u32(sm);
  const uint32_t Wb = sbase;

  int tid = threadIdx.x;
  int lane = tid & 31, w = tid >> 5;

  const uint32_t Eb = sbase + 32768 + (uint32_t)w*8448;
  float* Dw = (float*)(sm + 32768 + w*8448);

  // ---- W1b -> smem fp16 once ----
  {
    int d = tid >> 1, hh = tid & 1;
    const float4* wr = (const float4*)(W1 + (size_t)d*2*DD + DD + hh*64);
    uint32_t sw = (uint32_t)(d & 7) << 4;
    char* dst = sm + d*256;
    #pragma unroll
    for (int i = 0; i < 8; i++){
      float4 v0 = wr[2*i], v1 = wr[2*i+1];
      uint4 q;
      q.x = h2u(__floats2half2_rn(v0.x, v0.y));
      q.y = h2u(__floats2half2_rn(v0.z, v0.w));
      q.z = h2u(__floats2half2_rn(v1.x, v1.y));
      q.w = h2u(__floats2half2_rn(v1.z, v1.w));
      *(uint4*)(dst + (((uint32_t)(hh*128 + i*16)) ^ sw)) = q;
    }
  }
  __syncthreads();   // only block barrier

  const uint32_t ln15 = lane & 15;
  const uint32_t sxor = (uint32_t)(lane & 7) << 4;
  const uint32_t kbl  = (uint32_t)(lane >> 4) << 4;
  const uint32_t baseA = Eb + ln15*256;
  const uint32_t baseB = Wb + ln15*256;

  const int r2 = lane >> 1, eh = lane & 1;
  char* edst = (char*)sm + 32768 + w*8448 + r2*256;
  const uint32_t esw = (uint32_t)(r2 & 7) << 4;

  int gw = blockIdx.x*8 + w;
  int s_lo = gw*CHUNK;
  int s_hi = s_lo + CHUNK; if (s_hi > SLICES) s_hi = SLICES;

  int curbatch = -1;
  int cur = -1;
  float tv[4];
  float run[4] = {0.f, 0.f, 0.f, 0.f};

  for (int slice = s_lo; slice < s_hi; slice++){
    int batch = slice >> 7;
    if (batch != curbatch){
      curbatch = batch;
      #pragma unroll
      for (int j = 0; j < 4; j++) tv[j] = g_T[batch*DD + lane + 32*j];
      // cur is already -1 at batch boundary (sentinel row ends each batch)
    }
    int rowbase = batch*RPB + (slice & 127)*16;

    // ---- gather 16 rows -> fp16 swizzled E ----
    int pv = g_perm[rowbase + r2];
    {
      int node = (pv >> 8) & 2047;
      const float4* src = (const float4*)(embs + ((size_t)batch*NN + node)*DD + eh*64);
      #pragma unroll
      for (int half = 0; half < 2; half++){
        float4 vv[8];
        #pragma unroll
        for (int i = 0; i < 8; i++) vv[i] = src[half*8 + i];
        #pragma unroll
        for (int i = 0; i < 4; i++){
          uint4 q;
          q.x = h2u(__floats2half2_rn(vv[2*i].x, vv[2*i].y));
          q.y = h2u(__floats2half2_rn(vv[2*i].z, vv[2*i].w));
          q.z = h2u(__floats2half2_rn(vv[2*i+1].x, vv[2*i+1].y));
          q.w = h2u(__floats2half2_rn(vv[2*i+1].z, vv[2*i+1].w));
          *(uint4*)(edst + (((uint32_t)(eh*128 + half*64 + i*16)) ^ esw)) = q;
        }
      }
    }
    __syncwarp();

    // ---- MMA: 16 x 128, K=128 ----
    float acc[16][4];
    #pragma unroll
    for (int i = 0; i < 16; i++){ acc[i][0]=0.f; acc[i][1]=0.f; acc[i][2]=0.f; acc[i][3]=0.f; }
    #pragma unroll
    for (int k0 = 0; k0 < 8; k0++){
      uint32_t ko = (((uint32_t)k0 << 5) | kbl) ^ sxor;
      uint32_t a0, a1, a2, a3;
      ldsm4(a0, a1, a2, a3, baseA + ko);
      uint32_t bad = baseB + ko;
      #pragma unroll
      for (int j = 0; j < 8; j++){
        uint32_t b0, b1, b2, b3;
        ldsm4(b0, b1, b2, b3, bad);
        bad += 16*256;
        mma16816(acc[2*j],   a0, a1, a2, a3, b0, b2);
        mma16816(acc[2*j+1], a0, a1, a2, a3, b1, b3);
      }
    }
    __syncwarp();   // E consumed; D may overwrite buffer

    // ---- one-pass D store: 16 rows x 132 ----
    {
      int r0 = lane >> 2;
      int c0 = 2*(lane & 3);
      #pragma unroll
      for (int nt = 0; nt < 16; nt++){
        *(float2*)(Dw + r0*132 + c0 + nt*8)     = make_float2(acc[nt][0], acc[nt][1]);
        *(float2*)(Dw + (r0+8)*132 + c0 + nt*8) = make_float2(acc[nt][2], acc[nt][3]);
      }
    }
    __syncwarp();

    // ---- epilogue: run-length reduce carried across slices ----
    #pragma unroll
    for (int r = 0; r < 16; r++){
      int pvr = __shfl_sync(0xffffffffu, pv, 2*r);
      int s = (pvr < 0) ? -1 : (pvr & 255);
      if (s != cur){
        if (cur >= 0){
          #pragma unroll
          for (int j = 0; j < 4; j++) atomicAdd(&g_acc[curbatch*DD + 0 + cur*DD + lane + 32*j - cur*DD], 0.f), void();
        }
        // (flush handled below to keep correct base)
      }
      if (s != cur){
        if (cur >= 0){
          #pragma unroll
          for (int j = 0; j < 4; j++) atomicAdd(&g_acc[cur*DD + lane + 32*j], run[j]);
        }
        run[0]=run[1]=run[2]=run[3]=0.f;
        cur = s;
      }
      if (s >= 0){
        #pragma unroll
        for (int j = 0; j < 4; j++)
          run[j] += fmaxf(Dw[r*132 + lane + 32*j] + tv[j], 0.f);
      }
    }
    __syncwarp();   // D reads done before next slice's E write
  }
  if (cur >= 0){
    #pragma unroll
    for (int j = 0; j < 4; j++) atomicAdd(&g_acc[cur*DD + lane + 32*j], run[j]);
  }
}

// ---------------- final ----------------
__global__ void __launch_bounds__(256) k_final(const float* __restrict__ W2,
                                               const float* __restrict__ b2,
                                               float* __restrict__ out){
  __shared__ float arow[DD];
  __shared__ int wsum[8];
  int s = blockIdx.x, t = threadIdx.x;
  int lane = t & 31, wrp = t >> 5;

  if (t < DD) arow[t] = g_acc[s*DD + t];
  int c = g_histT[s*BB + t];
  #pragma unroll
  for (int o = 16; o > 0; o >>= 1) c += __shfl_xor_sync(0xffffffffu, c, o);
  if (lane == 0) wsum[wrp] = c;
  __syncthreads();
  int cnt = wsum[0] + wsum[1] + wsum[2] + wsum[3] + wsum[4] + wsum[5] + wsum[6] + wsum[7];

  int d = t >> 1, half = t & 1;
  const float* ww = W2 + (size_t)d*DD + half*64;
  const float* ar = arow + half*64;
  float r = 0.f;
  #pragma unroll
  for (int j = 0; j < 64; j++) r += ww[j]*ar[j];
  r += __shfl_xor_sync(0xffffffffu, r, 1);
  if (half == 0) out[s*DD + d] = r + b2[d]*(float)cnt;
}

// ---------------- launch ----------------
extern "C" void kernel_launch(void* const* d_in, const int* in_sizes, int n_in,
                              void* d_out, int out_size){
  const float* embs = (const float*)d_in[0];
  const float* W1   = (const float*)d_in[1];
  const float* b1   = (const float*)d_in[2];
  const float* W2   = (const float*)d_in[3];
  const float* b2   = (const float*)d_in[4];
  const int*   bidx = (const int*)d_in[5];
  float* out = (float*)d_out;

  cudaFuncSetAttribute(k_main, cudaFuncAttributeMaxDynamicSharedMemorySize, SMEM_MAIN);

  k_prep <<<BB, 512>>>(bidx, embs, W1, b1);
  k_main <<<GRID_MAIN, 256, SMEM_MAIN>>>(embs, W1);
  k_final<<<BB, 256>>>(W2, b2, out);
}

// round 11
// speedup vs baseline: 1.0016x; 1.0016x over previous
#include <cuda_runtime.h>
#include <cuda_fp16.h>
#include <cstdint>

#define BB 256
#define NN 2048
#define DD 128
#define RPB 2048
#define SLICES (BB*128)           // 32768 16-row slices
#define GRID_MAIN 296             // 2 persistent CTAs/SM
#define NWARPS (GRID_MAIN*8)      // 2368 warps
#define CHUNK 14                  // ceil(SLICES / NWARPS)
// smem: W16 [0,32768) | per-warp D/E overlay 8 x 8448 [32768,100352)
#define SMEM_MAIN 100352

// ---------------- device scratch ----------------
__device__ float g_acc[BB*DD];
__device__ int   g_histT[BB*BB];   // [seg][batch]
__device__ int   g_perm[BB*RPB];   // packed (node<<8)|seg ; sentinel sign bit
__device__ float g_T[BB*DD];

// ---------------- helpers ----------------
static __device__ __forceinline__ uint32_t smem_u32(const void* p){
  uint32_t a;
  asm("{ .reg .u64 t; cvta.to.shared.u64 t, %1; cvt.u32.u64 %0, t; }" : "=r"(a) : "l"(p));
  return a;
}
static __device__ __forceinline__ uint32_t h2u(__half2 h){
  union { __half2 h; uint32_t u; } c; c.h = h; return c.u;
}
static __device__ __forceinline__ void ldsm4(uint32_t &r0, uint32_t &r1, uint32_t &r2, uint32_t &r3, uint32_t a){
  asm volatile("ldmatrix.sync.aligned.m8n8.x4.shared.b16 {%0,%1,%2,%3}, [%4];"
    : "=r"(r0), "=r"(r1), "=r"(r2), "=r"(r3) : "r"(a));
}
static __device__ __forceinline__ void mma16816(float* c, uint32_t a0, uint32_t a1, uint32_t a2, uint32_t a3,
                                                uint32_t b0, uint32_t b1){
  asm volatile("mma.sync.aligned.m16n8k16.row.col.f32.f16.f16.f32 "
    "{%0,%1,%2,%3}, {%4,%5,%6,%7}, {%8,%9}, {%0,%1,%2,%3};"
    : "+f"(c[0]), "+f"(c[1]), "+f"(c[2]), "+f"(c[3])
    : "r"(a0), "r"(a1), "r"(a2), "r"(a3), "r"(b0), "r"(b1));
}

// ---------------- fused prep: 256 blocks; hist+scan+scatter+prepT per batch ----------------
__global__ void __launch_bounds__(512) k_prep(const int* __restrict__ bidx,
                                              const float* __restrict__ embs,
                                              const float* __restrict__ W1,
                                              const float* __restrict__ b1){
  int b = blockIdx.x, t = threadIdx.x;
  __shared__ int sb[NN];
  __shared__ float tg[DD];
  __shared__ int h[BB];
  __shared__ int wsum[8];

  if (t < BB) h[t] = 0;
  if (t < DD){ g_acc[b*DD + t] = 0.f; tg[t] = embs[(size_t)b*NN*DD + t]; }
  for (int i = t; i < NN-1; i += 512) sb[i] = bidx[b*NN + 1 + i];
  __syncthreads();

  // prepT: d = t>>2, k-quarter = t&3
  {
    int d = t >> 2, kq = t & 3;
    const float* w = W1 + (size_t)d*2*DD + kq*32;
    const float* tgp = tg + kq*32;
    float s = 0.f;
    #pragma unroll
    for (int k = 0; k < 32; k++) s += w[k]*tgp[k];
    s += __shfl_xor_sync(0xffffffffu, s, 1);
    s += __shfl_xor_sync(0xffffffffu, s, 2);
    if (kq == 0) g_T[b*DD + d] = s + b1[d];
  }

  for (int i = t; i < NN-1; i += 512)
    atomicAdd(&h[sb[i]], 1);
  __syncthreads();

  int lane = t & 31, wrp = t >> 5;
  int v = 0, x = 0;
  if (t < BB){ v = h[t]; g_histT[t*BB + b] = v; }
  x = v;
  #pragma unroll
  for (int o = 1; o < 32; o <<= 1){
    int y = __shfl_up_sync(0xffffffffu, x, o);
    if (lane >= o) x += y;
  }
  if (t < BB && lane == 31) wsum[wrp] = x;
  __syncthreads();
  if (t < 32){
    int s = (t < 8) ? wsum[t] : 0;
    #pragma unroll
    for (int o = 1; o < 8; o <<= 1){
      int y = __shfl_up_sync(0xffffffffu, s, o);
      if (t >= o) s += y;
    }
    if (t < 8) wsum[t] = s;
  }
  __syncthreads();
  if (t < BB){
    int off = (wrp > 0) ? wsum[wrp-1] : 0;
    h[t] = off + x - v;
  }
  __syncthreads();
  for (int i = t; i < NN-1; i += 512){
    int s = sb[i];
    int pos = atomicAdd(&h[s], 1);
    g_perm[b*RPB + pos] = ((1 + i) << 8) | s;
  }
  if (t == 0) g_perm[b*RPB + NN-1] = (int)(0x80000000u | (1u << 8));
}

// ---------------- main: warp-autonomous contiguous slice chunks ----------------
__global__ void __launch_bounds__(256, 2) k_main(const float* __restrict__ embs,
                                                 const float* __restrict__ W1){
  extern __shared__ char sm[];
  uint32_t sbase = smem_u32(sm);
  const uint32_t Wb = sbase;

  int tid = threadIdx.x;
  int lane = tid & 31, w = tid >> 5;

  const uint32_t Eb = sbase + 32768 + (uint32_t)w*8448;
  float* Dw = (float*)(sm + 32768 + w*8448);

  // ---- W1b -> smem fp16 once ----
  {
    int d = tid >> 1, hh = tid & 1;
    const float4* wr = (const float4*)(W1 + (size_t)d*2*DD + DD + hh*64);
    uint32_t sw = (uint32_t)(d & 7) << 4;
    char* dst = sm + d*256;
    #pragma unroll
    for (int i = 0; i < 8; i++){
      float4 v0 = wr[2*i], v1 = wr[2*i+1];
      uint4 q;
      q.x = h2u(__floats2half2_rn(v0.x, v0.y));
      q.y = h2u(__floats2half2_rn(v0.z, v0.w));
      q.z = h2u(__floats2half2_rn(v1.x, v1.y));
      q.w = h2u(__floats2half2_rn(v1.z, v1.w));
      *(uint4*)(dst + (((uint32_t)(hh*128 + i*16)) ^ sw)) = q;
    }
  }
  __syncthreads();   // only block barrier

  const uint32_t ln15 = lane & 15;
  const uint32_t sxor = (uint32_t)(lane & 7) << 4;
  const uint32_t kbl  = (uint32_t)(lane >> 4) << 4;
  const uint32_t baseA = Eb + ln15*256;
  const uint32_t baseB = Wb + ln15*256;

  const int r2 = lane >> 1, eh = lane & 1;
  char* edst = (char*)sm + 32768 + w*8448 + r2*256;
  const uint32_t esw = (uint32_t)(r2 & 7) << 4;

  int gw = blockIdx.x*8 + w;
  int s_lo = gw*CHUNK;
  int s_hi = s_lo + CHUNK; if (s_hi > SLICES) s_hi = SLICES;

  int curbatch = -1;
  int cur = -1;
  float tv[4];
  float run[4] = {0.f, 0.f, 0.f, 0.f};

  for (int slice = s_lo; slice < s_hi; slice++){
    int batch = slice >> 7;
    if (batch != curbatch){
      curbatch = batch;
      #pragma unroll
      for (int j = 0; j < 4; j++) tv[j] = g_T[batch*DD + lane + 32*j];
      // cur is already -1 here: each batch ends with a sentinel row
    }
    int rowbase = batch*RPB + (slice & 127)*16;

    __syncwarp();   // previous slice's D reads complete before E overwrite

    // ---- gather 16 rows -> fp16 swizzled E ----
    int pv = g_perm[rowbase + r2];
    {
      int node = (pv >> 8) & 2047;
      const float4* src = (const float4*)(embs + ((size_t)batch*NN + node)*DD + eh*64);
      #pragma unroll
      for (int half = 0; half < 2; half++){
        float4 vv[8];
        #pragma unroll
        for (int i = 0; i < 8; i++) vv[i] = src[half*8 + i];
        #pragma unroll
        for (int i = 0; i < 4; i++){
          uint4 q;
          q.x = h2u(__floats2half2_rn(vv[2*i].x, vv[2*i].y));
          q.y = h2u(__floats2half2_rn(vv[2*i].z, vv[2*i].w));
          q.z = h2u(__floats2half2_rn(vv[2*i+1].x, vv[2*i+1].y));
          q.w = h2u(__floats2half2_rn(vv[2*i+1].z, vv[2*i+1].w));
          *(uint4*)(edst + (((uint32_t)(eh*128 + half*64 + i*16)) ^ esw)) = q;
        }
      }
    }
    __syncwarp();

    // ---- MMA: 16 x 128, K=128 ----
    float acc[16][4];
    #pragma unroll
    for (int i = 0; i < 16; i++){ acc[i][0]=0.f; acc[i][1]=0.f; acc[i][2]=0.f; acc[i][3]=0.f; }
    #pragma unroll
    for (int k0 = 0; k0 < 8; k0++){
      uint32_t ko = (((uint32_t)k0 << 5) | kbl) ^ sxor;
      uint32_t a0, a1, a2, a3;
      ldsm4(a0, a1, a2, a3, baseA + ko);
      uint32_t bad = baseB + ko;
      #pragma unroll
      for (int j = 0; j < 8; j++){
        uint32_t b0, b1, b2, b3;
        ldsm4(b0, b1, b2, b3, bad);
        bad += 16*256;
        mma16816(acc[2*j],   a0, a1, a2, a3, b0, b2);
        mma16816(acc[2*j+1], a0, a1, a2, a3, b1, b3);
      }
    }
    __syncwarp();   // E consumed; D may overwrite buffer

    // ---- one-pass D store: 16 rows x 132 ----
    {
      int r0 = lane >> 2;
      int c0 = 2*(lane & 3);
      #pragma unroll
      for (int nt = 0; nt < 16; nt++){
        *(float2*)(Dw + r0*132 + c0 + nt*8)     = make_float2(acc[nt][0], acc[nt][1]);
        *(float2*)(Dw + (r0+8)*132 + c0 + nt*8) = make_float2(acc[nt][2], acc[nt][3]);
      }
    }
    __syncwarp();

    // ---- epilogue: run-length reduce, state carried across slices ----
    #pragma unroll
    for (int r = 0; r < 16; r++){
      int pvr = __shfl_sync(0xffffffffu, pv, 2*r);
      int s = (pvr < 0) ? -1 : (pvr & 255);
      if (s != cur){
        if (cur >= 0){
          #pragma unroll
          for (int j = 0; j < 4; j++) atomicAdd(&g_acc[cur*DD + lane + 32*j], run[j]);
        }
        run[0]=run[1]=run[2]=run[3]=0.f;
        cur = s;
      }
      if (s >= 0){
        #pragma unroll
        for (int j = 0; j < 4; j++)
          run[j] += fmaxf(Dw[r*132 + lane + 32*j] + tv[j], 0.f);
      }
    }
  }
  if (cur >= 0){
    #pragma unroll
    for (int j = 0; j < 4; j++) atomicAdd(&g_acc[cur*DD + lane + 32*j], run[j]);
  }
}

// ---------------- final ----------------
__global__ void __launch_bounds__(256) k_final(const float* __restrict__ W2,
                                               const float* __restrict__ b2,
                                               float* __restrict__ out){
  __shared__ float arow[DD];
  __shared__ int wsum[8];
  int s = blockIdx.x, t = threadIdx.x;
  int lane = t & 31, wrp = t >> 5;

  if (t < DD) arow[t] = g_acc[s*DD + t];
  int c = g_histT[s*BB + t];
  #pragma unroll
  for (int o = 16; o > 0; o >>= 1) c += __shfl_xor_sync(0xffffffffu, c, o);
  if (lane == 0) wsum[wrp] = c;
  __syncthreads();
  int cnt = wsum[0] + wsum[1] + wsum[2] + wsum[3] + wsum[4] + wsum[5] + wsum[6] + wsum[7];

  int d = t >> 1, half = t & 1;
  const float* ww = W2 + (size_t)d*DD + half*64;
  const float* ar = arow + half*64;
  float r = 0.f;
  #pragma unroll
  for (int j = 0; j < 64; j++) r += ww[j]*ar[j];
  r += __shfl_xor_sync(0xffffffffu, r, 1);
  if (half == 0) out[s*DD + d] = r + b2[d]*(float)cnt;
}

// ---------------- launch ----------------
extern "C" void kernel_launch(void* const* d_in, const int* in_sizes, int n_in,
                              void* d_out, int out_size){
  const float* embs = (const float*)d_in[0];
  const float* W1   = (const float*)d_in[1];
  const float* b1   = (const float*)d_in[2];
  const float* W2   = (const float*)d_in[3];
  const float* b2   = (const float*)d_in[4];
  const int*   bidx = (const int*)d_in[5];
  float* out = (float*)d_out;

  cudaFuncSetAttribute(k_main, cudaFuncAttributeMaxDynamicSharedMemorySize, SMEM_MAIN);

  k_prep <<<BB, 512>>>(bidx, embs, W1, b1);
  k_main <<<GRID_MAIN, 256, SMEM_MAIN>>>(embs, W1);
  k_final<<<BB, 256>>>(W2, b2, out);
}

// round 12
// speedup vs baseline: 1.0794x; 1.0777x over previous
#include <cuda_runtime.h>
#include <cuda_fp16.h>
#include <cstdint>

#define BB 256
#define NN 2048
#define DD 128
#define RPB 2048
#define SLICES (BB*128)           // 32768 16-row slices
#define GRID_MAIN 296             // 2 persistent CTAs/SM
#define WSTRIDE (GRID_MAIN*8)
// smem: W16 [0,32768) | per-warp E/D overlay 8 x 4224 [32768,66560)
#define SMEM_MAIN 66560

// ---------------- device scratch ----------------
__device__ float g_acc[BB*DD];
__device__ int   g_histT[BB*BB];   // [seg][batch]
__device__ int   g_perm[BB*RPB];   // packed (node<<8)|seg ; sentinel sign bit
__device__ float g_T[BB*DD];

// ---------------- helpers ----------------
static __device__ __forceinline__ uint32_t smem_u32(const void* p){
  uint32_t a;
  asm("{ .reg .u64 t; cvta.to.shared.u64 t, %1; cvt.u32.u64 %0, t; }" : "=r"(a) : "l"(p));
  return a;
}
static __device__ __forceinline__ uint32_t h2u(__half2 h){
  union { __half2 h; uint32_t u; } c; c.h = h; return c.u;
}
static __device__ __forceinline__ void ldsm4(uint32_t &r0, uint32_t &r1, uint32_t &r2, uint32_t &r3, uint32_t a){
  asm volatile("ldmatrix.sync.aligned.m8n8.x4.shared.b16 {%0,%1,%2,%3}, [%4];"
    : "=r"(r0), "=r"(r1), "=r"(r2), "=r"(r3) : "r"(a));
}
static __device__ __forceinline__ void mma16816(float* c, uint32_t a0, uint32_t a1, uint32_t a2, uint32_t a3,
                                                uint32_t b0, uint32_t b1){
  asm volatile("mma.sync.aligned.m16n8k16.row.col.f32.f16.f16.f32 "
    "{%0,%1,%2,%3}, {%4,%5,%6,%7}, {%8,%9}, {%0,%1,%2,%3};"
    : "+f"(c[0]), "+f"(c[1]), "+f"(c[2]), "+f"(c[3])
    : "r"(a0), "r"(a1), "r"(a2), "r"(a3), "r"(b0), "r"(b1));
}

// ---------------- fused prep: 256 blocks; hist+scan+scatter+prepT per batch ----------------
__global__ void __launch_bounds__(512) k_prep(const int* __restrict__ bidx,
                                              const float* __restrict__ embs,
                                              const float* __restrict__ W1,
                                              const float* __restrict__ b1){
  int b = blockIdx.x, t = threadIdx.x;
  __shared__ int sb[NN];
  __shared__ float tg[DD];
  __shared__ int h[BB];
  __shared__ int wsum[8];

  if (t < BB) h[t] = 0;
  if (t < DD){ g_acc[b*DD + t] = 0.f; tg[t] = embs[(size_t)b*NN*DD + t]; }
  for (int i = t; i < NN-1; i += 512) sb[i] = bidx[b*NN + 1 + i];
  __syncthreads();

  // prepT: d = t>>2, k-quarter = t&3
  {
    int d = t >> 2, kq = t & 3;
    const float* w = W1 + (size_t)d*2*DD + kq*32;
    const float* tgp = tg + kq*32;
    float s = 0.f;
    #pragma unroll
    for (int k = 0; k < 32; k++) s += w[k]*tgp[k];
    s += __shfl_xor_sync(0xffffffffu, s, 1);
    s += __shfl_xor_sync(0xffffffffu, s, 2);
    if (kq == 0) g_T[b*DD + d] = s + b1[d];
  }

  for (int i = t; i < NN-1; i += 512)
    atomicAdd(&h[sb[i]], 1);
  __syncthreads();

  int lane = t & 31, wrp = t >> 5;
  int v = 0, x = 0;
  if (t < BB){ v = h[t]; g_histT[t*BB + b] = v; }
  x = v;
  #pragma unroll
  for (int o = 1; o < 32; o <<= 1){
    int y = __shfl_up_sync(0xffffffffu, x, o);
    if (lane >= o) x += y;
  }
  if (t < BB && lane == 31) wsum[wrp] = x;
  __syncthreads();
  if (t < 32){
    int s = (t < 8) ? wsum[t] : 0;
    #pragma unroll
    for (int o = 1; o < 8; o <<= 1){
      int y = __shfl_up_sync(0xffffffffu, s, o);
      if (t >= o) s += y;
    }
    if (t < 8) wsum[t] = s;
  }
  __syncthreads();
  if (t < BB){
    int off = (wrp > 0) ? wsum[wrp-1] : 0;
    h[t] = off + x - v;
  }
  __syncthreads();
  for (int i = t; i < NN-1; i += 512){
    int s = sb[i];
    int pos = atomicAdd(&h[s], 1);
    g_perm[b*RPB + pos] = ((1 + i) << 8) | s;
  }
  if (t == 0) g_perm[b*RPB + NN-1] = (int)(0x80000000u | (1u << 8));
}

// ---------------- main: warp-autonomous strided 16-row slices (R9 structure) ----------------
__global__ void __launch_bounds__(256, 2) k_main(const float* __restrict__ embs,
                                                 const float* __restrict__ W1){
  extern __shared__ char sm[];
  uint32_t sbase = smem_u32(sm);
  const uint32_t Wb = sbase;

  int tid = threadIdx.x;
  int lane = tid & 31, w = tid >> 5;

  const uint32_t Eb = sbase + 32768 + (uint32_t)w*4224;   // E and D share this buffer
  float* Dw = (float*)(sm + 32768 + w*4224);

  // ---- W1b -> smem fp16 once ----
  {
    int d = tid >> 1, hh = tid & 1;
    const float4* wr = (const float4*)(W1 + (size_t)d*2*DD + DD + hh*64);
    uint32_t sw = (uint32_t)(d & 7) << 4;
    char* dst = sm + d*256;
    #pragma unroll
    for (int i = 0; i < 8; i++){
      float4 v0 = wr[2*i], v1 = wr[2*i+1];
      uint4 q;
      q.x = h2u(__floats2half2_rn(v0.x, v0.y));
      q.y = h2u(__floats2half2_rn(v0.z, v0.w));
      q.z = h2u(__floats2half2_rn(v1.x, v1.y));
      q.w = h2u(__floats2half2_rn(v1.z, v1.w));
      *(uint4*)(dst + (((uint32_t)(hh*128 + i*16)) ^ sw)) = q;
    }
  }
  __syncthreads();   // only block barrier

  const uint32_t ln15 = lane & 15;
  const uint32_t sxor = (uint32_t)(lane & 7) << 4;
  const uint32_t kbl  = (uint32_t)(lane >> 4) << 4;
  const uint32_t baseA = Eb + ln15*256;
  const uint32_t baseB = Wb + ln15*256;

  const int r2 = lane >> 1, eh = lane & 1;
  char* edst = (char*)sm + 32768 + w*4224 + r2*256;
  const uint32_t esw = (uint32_t)(r2 & 7) << 4;

  for (int slice = blockIdx.x*8 + w; slice < SLICES; slice += WSTRIDE){
    int batch = slice >> 7;
    int rowbase = batch*RPB + (slice & 127)*16;

    // ---- gather 16 rows -> fp16 swizzled E ----
    int pv = g_perm[rowbase + r2];
    {
      int node = (pv >> 8) & 2047;
      const float4* src = (const float4*)(embs + ((size_t)batch*NN + node)*DD + eh*64);
      #pragma unroll
      for (int half = 0; half < 2; half++){
        float4 vv[8];
        #pragma unroll
        for (int i = 0; i < 8; i++) vv[i] = src[half*8 + i];
        #pragma unroll
        for (int i = 0; i < 4; i++){
          uint4 q;
          q.x = h2u(__floats2half2_rn(vv[2*i].x, vv[2*i].y));
          q.y = h2u(__floats2half2_rn(vv[2*i].z, vv[2*i].w));
          q.z = h2u(__floats2half2_rn(vv[2*i+1].x, vv[2*i+1].y));
          q.w = h2u(__floats2half2_rn(vv[2*i+1].z, vv[2*i+1].w));
          *(uint4*)(edst + (((uint32_t)(eh*128 + half*64 + i*16)) ^ esw)) = q;
        }
      }
    }
    __syncwarp();

    // ---- MMA: 16 rows x 128 cols, K=128 ----
    float acc[16][4];
    #pragma unroll
    for (int i = 0; i < 16; i++){ acc[i][0]=0.f; acc[i][1]=0.f; acc[i][2]=0.f; acc[i][3]=0.f; }
    #pragma unroll
    for (int k0 = 0; k0 < 8; k0++){
      uint32_t ko = (((uint32_t)k0 << 5) | kbl) ^ sxor;
      uint32_t a0, a1, a2, a3;
      ldsm4(a0, a1, a2, a3, baseA + ko);
      uint32_t bad = baseB + ko;
      #pragma unroll
      for (int j = 0; j < 8; j++){
        uint32_t b0, b1, b2, b3;
        ldsm4(b0, b1, b2, b3, bad);
        bad += 16*256;
        mma16816(acc[2*j],   a0, a1, a2, a3, b0, b2);
        mma16816(acc[2*j+1], a0, a1, a2, a3, b1, b3);
      }
    }
    __syncwarp();   // all E consumed; D may overwrite buffer

    // ---- epilogue: two 8-row passes through warp-private D (overlaid on E) ----
    float tv[4];
    #pragma unroll
    for (int j = 0; j < 4; j++) tv[j] = g_T[batch*DD + lane + 32*j];

    int r0 = lane >> 2;
    int c0 = 2*(lane & 3);
    int cur = -1;
    float run[4] = {0.f, 0.f, 0.f, 0.f};

    #pragma unroll
    for (int nt = 0; nt < 16; nt++)
      *(float2*)(Dw + r0*132 + c0 + nt*8) = make_float2(acc[nt][0], acc[nt][1]);
    __syncwarp();
    #pragma unroll
    for (int r = 0; r < 8; r++){
      int pvr = __shfl_sync(0xffffffffu, pv, 2*r);
      int s = (pvr < 0) ? -1 : (pvr & 255);
      if (s != cur){
        if (cur >= 0){
          #pragma unroll
          for (int j = 0; j < 4; j++) atomicAdd(&g_acc[cur*DD + lane + 32*j], run[j]);
        }
        run[0]=run[1]=run[2]=run[3]=0.f;
        cur = s;
      }
      if (s >= 0){
        #pragma unroll
        for (int j = 0; j < 4; j++)
          run[j] += fmaxf(Dw[r*132 + lane + 32*j] + tv[j], 0.f);
      }
    }
    __syncwarp();

    #pragma unroll
    for (int nt = 0; nt < 16; nt++)
      *(float2*)(Dw + r0*132 + c0 + nt*8) = make_float2(acc[nt][2], acc[nt][3]);
    __syncwarp();
    #pragma unroll
    for (int r = 0; r < 8; r++){
      int pvr = __shfl_sync(0xffffffffu, pv, 2*(r + 8));
      int s = (pvr < 0) ? -1 : (pvr & 255);
      if (s != cur){
        if (cur >= 0){
          #pragma unroll
          for (int j = 0; j < 4; j++) atomicAdd(&g_acc[cur*DD + lane + 32*j], run[j]);
        }
        run[0]=run[1]=run[2]=run[3]=0.f;
        cur = s;
      }
      if (s >= 0){
        #pragma unroll
        for (int j = 0; j < 4; j++)
          run[j] += fmaxf(Dw[r*132 + lane + 32*j] + tv[j], 0.f);
      }
    }
    if (cur >= 0){
      #pragma unroll
      for (int j = 0; j < 4; j++) atomicAdd(&g_acc[cur*DD + lane + 32*j], run[j]);
    }
    __syncwarp();   // D reads done before next slice's E write
  }
}

// ---------------- final ----------------
__global__ void __launch_bounds__(256) k_final(const float* __restrict__ W2,
                                               const float* __restrict__ b2,
                                               float* __restrict__ out){
  __shared__ float arow[DD];
  __shared__ int wsum[8];
  int s = blockIdx.x, t = threadIdx.x;
  int lane = t & 31, wrp = t >> 5;

  if (t < DD) arow[t] = g_acc[s*DD + t];
  int c = g_histT[s*BB + t];
  #pragma unroll
  for (int o = 16; o > 0; o >>= 1) c += __shfl_xor_sync(0xffffffffu, c, o);
  if (lane == 0) wsum[wrp] = c;
  __syncthreads();
  int cnt = wsum[0] + wsum[1] + wsum[2] + wsum[3] + wsum[4] + wsum[5] + wsum[6] + wsum[7];

  int d = t >> 1, half = t & 1;
  const float* ww = W2 + (size_t)d*DD + half*64;
  const float* ar = arow + half*64;
  float r = 0.f;
  #pragma unroll
  for (int j = 0; j < 64; j++) r += ww[j]*ar[j];
  r += __shfl_xor_sync(0xffffffffu, r, 1);
  if (half == 0) out[s*DD + d] = r + b2[d]*(float)cnt;
}

// ---------------- launch ----------------
extern "C" void kernel_launch(void* const* d_in, const int* in_sizes, int n_in,
                              void* d_out, int out_size){
  const float* embs = (const float*)d_in[0];
  const float* W1   = (const float*)d_in[1];
  const float* b1   = (const float*)d_in[2];
  const float* W2   = (const float*)d_in[3];
  const float* b2   = (const float*)d_in[4];
  const int*   bidx = (const int*)d_in[5];
  float* out = (float*)d_out;

  cudaFuncSetAttribute(k_main, cudaFuncAttributeMaxDynamicSharedMemorySize, SMEM_MAIN);

  k_prep <<<BB, 512>>>(bidx, embs, W1, b1);
  k_main <<<GRID_MAIN, 256, SMEM_MAIN>>>(embs, W1);
  k_final<<<BB, 256>>>(W2, b2, out);
}

// round 13
// speedup vs baseline: 1.1644x; 1.0788x over previous
#include <cuda_runtime.h>
#include <cuda_fp16.h>
#include <cstdint>

#define BB 256
#define NN 2048
#define DD 128
#define RPB 2048
#define SLICES (BB*128)           // 32768 16-row slices
#define GRID_MAIN 296             // 2 persistent CTAs/SM
#define WSTRIDE (GRID_MAIN*8)
// k_main smem: W16 [0,32768) | per-warp E/D overlay 8 x 4224 [32768,66560)
#define SMEM_MAIN 66560
// k_prep smem: W1s 128x132 f32 [0,67584) | sb 2048 int [67584,75776) | tg 132 f32 (padded 4x33)
//              [75776,76320) | h 256 int [76320,77344) | wsum [77344,77376)
#define SMEM_PREP 77376

// ---------------- device scratch ----------------
__device__ float g_acc[BB*DD];
__device__ int   g_histT[BB*BB];   // [seg][batch]
__device__ int   g_perm[BB*RPB];   // packed (node<<8)|seg ; sentinel sign bit
__device__ float g_T[BB*DD];

// ---------------- helpers ----------------
static __device__ __forceinline__ uint32_t smem_u32(const void* p){
  uint32_t a;
  asm("{ .reg .u64 t; cvta.to.shared.u64 t, %1; cvt.u32.u64 %0, t; }" : "=r"(a) : "l"(p));
  return a;
}
static __device__ __forceinline__ uint32_t h2u(__half2 h){
  union { __half2 h; uint32_t u; } c; c.h = h; return c.u;
}
static __device__ __forceinline__ void ldsm4(uint32_t &r0, uint32_t &r1, uint32_t &r2, uint32_t &r3, uint32_t a){
  asm volatile("ldmatrix.sync.aligned.m8n8.x4.shared.b16 {%0,%1,%2,%3}, [%4];"
    : "=r"(r0), "=r"(r1), "=r"(r2), "=r"(r3) : "r"(a));
}
static __device__ __forceinline__ void mma16816(float* c, uint32_t a0, uint32_t a1, uint32_t a2, uint32_t a3,
                                                uint32_t b0, uint32_t b1){
  asm volatile("mma.sync.aligned.m16n8k16.row.col.f32.f16.f16.f32 "
    "{%0,%1,%2,%3}, {%4,%5,%6,%7}, {%8,%9}, {%0,%1,%2,%3};"
    : "+f"(c[0]), "+f"(c[1]), "+f"(c[2]), "+f"(c[3])
    : "r"(a0), "r"(a1), "r"(a2), "r"(a3), "r"(b0), "r"(b1));
}

// ---------------- fused prep: coalesced W1a smem staging ----------------
__global__ void __launch_bounds__(512) k_prep(const int* __restrict__ bidx,
                                              const float* __restrict__ embs,
                                              const float* __restrict__ W1,
                                              const float* __restrict__ b1){
  extern __shared__ char spr[];
  float* W1s = (float*)spr;                    // [128][132] padded
  int*   sb  = (int*)(spr + 67584);
  float* tgp = (float*)(spr + 75776);          // [4][33] padded target
  int*   h   = (int*)(spr + 76320);
  int*   wsum= (int*)(spr + 77344);

  int b = blockIdx.x, t = threadIdx.x;

  // coalesced W1a load: 4096 float4s, one row (512B span) per warp-iteration
  {
    const float4* W1f4 = (const float4*)W1;    // row stride 64 float4s (256 floats)
    #pragma unroll
    for (int j = 0; j < 8; j++){
      int idx = t + j*512;
      int row = idx >> 5, c4 = idx & 31;       // first 128 floats of the row = W1a
      float4 v = W1f4[row*64 + c4];
      *(float4*)(W1s + row*132 + c4*4) = v;
    }
  }
  if (t < BB) h[t] = 0;
  if (t < DD){
    g_acc[b*DD + t] = 0.f;
    float v = embs[(size_t)b*NN*DD + t];       // target row (node 0)
    tgp[(t >> 5)*33 + (t & 31)] = v;           // padded: conflict-free reads
  }
  for (int i = t; i < NN-1; i += 512) sb[i] = bidx[b*NN + 1 + i];
  __syncthreads();

  // prepT from smem: d = t>>2, kq = t&3 (conflict-free via 132/33 padding)
  {
    int d = t >> 2, kq = t & 3;
    const float* w = W1s + d*132 + kq*32;
    const float* tq = tgp + kq*33;
    float s = 0.f;
    #pragma unroll
    for (int k = 0; k < 32; k++) s += w[k]*tq[k];
    s += __shfl_xor_sync(0xffffffffu, s, 1);
    s += __shfl_xor_sync(0xffffffffu, s, 2);
    if (kq == 0) g_T[b*DD + d] = s + b1[d];
  }

  for (int i = t; i < NN-1; i += 512)
    atomicAdd(&h[sb[i]], 1);
  __syncthreads();

  int lane = t & 31, wrp = t >> 5;
  int v = 0, x = 0;
  if (t < BB){ v = h[t]; g_histT[t*BB + b] = v; }
  x = v;
  #pragma unroll
  for (int o = 1; o < 32; o <<= 1){
    int y = __shfl_up_sync(0xffffffffu, x, o);
    if (lane >= o) x += y;
  }
  if (t < BB && lane == 31) wsum[wrp] = x;
  __syncthreads();
  if (t < 32){
    int s = (t < 8) ? wsum[t] : 0;
    #pragma unroll
    for (int o = 1; o < 8; o <<= 1){
      int y = __shfl_up_sync(0xffffffffu, s, o);
      if (t >= o) s += y;
    }
    if (t < 8) wsum[t] = s;
  }
  __syncthreads();
  if (t < BB){
    int off = (wrp > 0) ? wsum[wrp-1] : 0;
    h[t] = off + x - v;
  }
  __syncthreads();
  for (int i = t; i < NN-1; i += 512){
    int s = sb[i];
    int pos = atomicAdd(&h[s], 1);
    g_perm[b*RPB + pos] = ((1 + i) << 8) | s;
  }
  if (t == 0) g_perm[b*RPB + NN-1] = (int)(0x80000000u | (1u << 8));
}

// ---------------- main: warp-autonomous strided 16-row slices (R9/R12 structure) ----------------
__global__ void __launch_bounds__(256, 2) k_main(const float* __restrict__ embs,
                                                 const float* __restrict__ W1){
  extern __shared__ char sm[];
  uint32_t sbase = smem_u32(sm);
  const uint32_t Wb = sbase;

  int tid = threadIdx.x;
  int lane = tid & 31, w = tid >> 5;

  const uint32_t Eb = sbase + 32768 + (uint32_t)w*4224;   // E and D share this buffer
  float* Dw = (float*)(sm + 32768 + w*4224);

  // ---- W1b -> smem fp16 once ----
  {
    int d = tid >> 1, hh = tid & 1;
    const float4* wr = (const float4*)(W1 + (size_t)d*2*DD + DD + hh*64);
    uint32_t sw = (uint32_t)(d & 7) << 4;
    char* dst = sm + d*256;
    #pragma unroll
    for (int i = 0; i < 8; i++){
      float4 v0 = wr[2*i], v1 = wr[2*i+1];
      uint4 q;
      q.x = h2u(__floats2half2_rn(v0.x, v0.y));
      q.y = h2u(__floats2half2_rn(v0.z, v0.w));
      q.z = h2u(__floats2half2_rn(v1.x, v1.y));
      q.w = h2u(__floats2half2_rn(v1.z, v1.w));
      *(uint4*)(dst + (((uint32_t)(hh*128 + i*16)) ^ sw)) = q;
    }
  }
  __syncthreads();   // only block barrier

  const uint32_t ln15 = lane & 15;
  const uint32_t sxor = (uint32_t)(lane & 7) << 4;
  const uint32_t kbl  = (uint32_t)(lane >> 4) << 4;
  const uint32_t baseA = Eb + ln15*256;
  const uint32_t baseB = Wb + ln15*256;

  const int r2 = lane >> 1, eh = lane & 1;
  char* edst = (char*)sm + 32768 + w*4224 + r2*256;
  const uint32_t esw = (uint32_t)(r2 & 7) << 4;

  for (int slice = blockIdx.x*8 + w; slice < SLICES; slice += WSTRIDE){
    int batch = slice >> 7;
    int rowbase = batch*RPB + (slice & 127)*16;

    // ---- gather 16 rows -> fp16 swizzled E ----
    int pv = g_perm[rowbase + r2];
    {
      int node = (pv >> 8) & 2047;
      const float4* src = (const float4*)(embs + ((size_t)batch*NN + node)*DD + eh*64);
      #pragma unroll
      for (int half = 0; half < 2; half++){
        float4 vv[8];
        #pragma unroll
        for (int i = 0; i < 8; i++) vv[i] = src[half*8 + i];
        #pragma unroll
        for (int i = 0; i < 4; i++){
          uint4 q;
          q.x = h2u(__floats2half2_rn(vv[2*i].x, vv[2*i].y));
          q.y = h2u(__floats2half2_rn(vv[2*i].z, vv[2*i].w));
          q.z = h2u(__floats2half2_rn(vv[2*i+1].x, vv[2*i+1].y));
          q.w = h2u(__floats2half2_rn(vv[2*i+1].z, vv[2*i+1].w));
          *(uint4*)(edst + (((uint32_t)(eh*128 + half*64 + i*16)) ^ esw)) = q;
        }
      }
    }
    __syncwarp();

    // ---- MMA: 16 rows x 128 cols, K=128 ----
    float acc[16][4];
    #pragma unroll
    for (int i = 0; i < 16; i++){ acc[i][0]=0.f; acc[i][1]=0.f; acc[i][2]=0.f; acc[i][3]=0.f; }
    #pragma unroll
    for (int k0 = 0; k0 < 8; k0++){
      uint32_t ko = (((uint32_t)k0 << 5) | kbl) ^ sxor;
      uint32_t a0, a1, a2, a3;
      ldsm4(a0, a1, a2, a3, baseA + ko);
      uint32_t bad = baseB + ko;
      #pragma unroll
      for (int j = 0; j < 8; j++){
        uint32_t b0, b1, b2, b3;
        ldsm4(b0, b1, b2, b3, bad);
        bad += 16*256;
        mma16816(acc[2*j],   a0, a1, a2, a3, b0, b2);
        mma16816(acc[2*j+1], a0, a1, a2, a3, b1, b3);
      }
    }
    __syncwarp();   // all E consumed; D may overwrite buffer

    // ---- epilogue: two 8-row passes through warp-private D (overlaid on E) ----
    float tv[4];
    #pragma unroll
    for (int j = 0; j < 4; j++) tv[j] = g_T[batch*DD + lane + 32*j];

    int r0 = lane >> 2;
    int c0 = 2*(lane & 3);
    int cur = -1;
    float run[4] = {0.f, 0.f, 0.f, 0.f};

    #pragma unroll
    for (int nt = 0; nt < 16; nt++)
      *(float2*)(Dw + r0*132 + c0 + nt*8) = make_float2(acc[nt][0], acc[nt][1]);
    __syncwarp();
    #pragma unroll
    for (int r = 0; r < 8; r++){
      int pvr = __shfl_sync(0xffffffffu, pv, 2*r);
      int s = (pvr < 0) ? -1 : (pvr & 255);
      if (s != cur){
        if (cur >= 0){
          #pragma unroll
          for (int j = 0; j < 4; j++) atomicAdd(&g_acc[cur*DD + lane + 32*j], run[j]);
        }
        run[0]=run[1]=run[2]=run[3]=0.f;
        cur = s;
      }
      if (s >= 0){
        #pragma unroll
        for (int j = 0; j < 4; j++)
          run[j] += fmaxf(Dw[r*132 + lane + 32*j] + tv[j], 0.f);
      }
    }
    __syncwarp();

    #pragma unroll
    for (int nt = 0; nt < 16; nt++)
      *(float2*)(Dw + r0*132 + c0 + nt*8) = make_float2(acc[nt][2], acc[nt][3]);
    __syncwarp();
    #pragma unroll
    for (int r = 0; r < 8; r++){
      int pvr = __shfl_sync(0xffffffffu, pv, 2*(r + 8));
      int s = (pvr < 0) ? -1 : (pvr & 255);
      if (s != cur){
        if (cur >= 0){
          #pragma unroll
          for (int j = 0; j < 4; j++) atomicAdd(&g_acc[cur*DD + lane + 32*j], run[j]);
        }
        run[0]=run[1]=run[2]=run[3]=0.f;
        cur = s;
      }
      if (s >= 0){
        #pragma unroll
        for (int j = 0; j < 4; j++)
          run[j] += fmaxf(Dw[r*132 + lane + 32*j] + tv[j], 0.f);
      }
    }
    if (cur >= 0){
      #pragma unroll
      for (int j = 0; j < 4; j++) atomicAdd(&g_acc[cur*DD + lane + 32*j], run[j]);
    }
    __syncwarp();   // D reads done before next slice's E write
  }
}

// ---------------- final ----------------
__global__ void __launch_bounds__(256) k_final(const float* __restrict__ W2,
                                               const float* __restrict__ b2,
                                               float* __restrict__ out){
  __shared__ float arow[DD];
  __shared__ int wsum[8];
  int s = blockIdx.x, t = threadIdx.x;
  int lane = t & 31, wrp = t >> 5;

  if (t < DD) arow[t] = g_acc[s*DD + t];
  int c = g_histT[s*BB + t];
  #pragma unroll
  for (int o = 16; o > 0; o >>= 1) c += __shfl_xor_sync(0xffffffffu, c, o);
  if (lane == 0) wsum[wrp] = c;
  __syncthreads();
  int cnt = wsum[0] + wsum[1] + wsum[2] + wsum[3] + wsum[4] + wsum[5] + wsum[6] + wsum[7];

  int d = t >> 1, half = t & 1;
  const float* ww = W2 + (size_t)d*DD + half*64;
  const float* ar = arow + half*64;
  float r = 0.f;
  #pragma unroll
  for (int j = 0; j < 64; j++) r += ww[j]*ar[j];
  r += __shfl_xor_sync(0xffffffffu, r, 1);
  if (half == 0) out[s*DD + d] = r + b2[d]*(float)cnt;
}

// ---------------- launch ----------------
extern "C" void kernel_launch(void* const* d_in, const int* in_sizes, int n_in,
                              void* d_out, int out_size){
  const float* embs = (const float*)d_in[0];
  const float* W1   = (const float*)d_in[1];
  const float* b1   = (const float*)d_in[2];
  const float* W2   = (const float*)d_in[3];
  const float* b2   = (const float*)d_in[4];
  const int*   bidx = (const int*)d_in[5];
  float* out = (float*)d_out;

  cudaFuncSetAttribute(k_prep, cudaFuncAttributeMaxDynamicSharedMemorySize, SMEM_PREP);
  cudaFuncSetAttribute(k_main, cudaFuncAttributeMaxDynamicSharedMemorySize, SMEM_MAIN);

  k_prep <<<BB, 512, SMEM_PREP>>>(bidx, embs, W1, b1);
  k_main <<<GRID_MAIN, 256, SMEM_MAIN>>>(embs, W1);
  k_final<<<BB, 256>>>(W2, b2, out);
}

// round 14
// speedup vs baseline: 1.1995x; 1.0301x over previous
#include <cuda_runtime.h>
#include <cuda_fp16.h>
#include <cstdint>

#define BB 256
#define NN 2048
#define DD 128
#define RPB 2048
#define SLICES32 (BB*64)          // 16384 32-row slices
#define GRID_MAIN 148             // 1 persistent CTA/SM (reg-heavy)
#define WSTRIDE (GRID_MAIN*8)     // 1184 warps
// k_main smem: W16 [0,32768) | per-warp E(8KB)/D(4224B overlay) 8 x 8448 [32768,100352)
#define SMEM_MAIN 100352
// k_prep smem layout unchanged from R13
#define SMEM_PREP 77376

// ---------------- device scratch ----------------
__device__ float g_acc[BB*DD];
__device__ int   g_histT[BB*BB];   // [seg][batch]
__device__ int   g_perm[BB*RPB];   // packed (node<<8)|seg ; sentinel sign bit
__device__ float g_T[BB*DD];

// ---------------- helpers ----------------
static __device__ __forceinline__ uint32_t smem_u32(const void* p){
  uint32_t a;
  asm("{ .reg .u64 t; cvta.to.shared.u64 t, %1; cvt.u32.u64 %0, t; }" : "=r"(a) : "l"(p));
  return a;
}
static __device__ __forceinline__ uint32_t h2u(__half2 h){
  union { __half2 h; uint32_t u; } c; c.h = h; return c.u;
}
static __device__ __forceinline__ void ldsm4(uint32_t &r0, uint32_t &r1, uint32_t &r2, uint32_t &r3, uint32_t a){
  asm volatile("ldmatrix.sync.aligned.m8n8.x4.shared.b16 {%0,%1,%2,%3}, [%4];"
    : "=r"(r0), "=r"(r1), "=r"(r2), "=r"(r3) : "r"(a));
}
static __device__ __forceinline__ void mma16816(float* c, uint32_t a0, uint32_t a1, uint32_t a2, uint32_t a3,
                                                uint32_t b0, uint32_t b1){
  asm volatile("mma.sync.aligned.m16n8k16.row.col.f32.f16.f16.f32 "
    "{%0,%1,%2,%3}, {%4,%5,%6,%7}, {%8,%9}, {%0,%1,%2,%3};"
    : "+f"(c[0]), "+f"(c[1]), "+f"(c[2]), "+f"(c[3])
    : "r"(a0), "r"(a1), "r"(a2), "r"(a3), "r"(b0), "r"(b1));
}

// ---------------- fused prep (R13, measured 12.8us) ----------------
__global__ void __launch_bounds__(512) k_prep(const int* __restrict__ bidx,
                                              const float* __restrict__ embs,
                                              const float* __restrict__ W1,
                                              const float* __restrict__ b1){
  extern __shared__ char spr[];
  float* W1s = (float*)spr;                    // [128][132] padded
  int*   sb  = (int*)(spr + 67584);
  float* tgp = (float*)(spr + 75776);          // [4][33] padded target
  int*   h   = (int*)(spr + 76320);
  int*   wsum= (int*)(spr + 77344);

  int b = blockIdx.x, t = threadIdx.x;

  {
    const float4* W1f4 = (const float4*)W1;
    #pragma unroll
    for (int j = 0; j < 8; j++){
      int idx = t + j*512;
      int row = idx >> 5, c4 = idx & 31;
      float4 v = W1f4[row*64 + c4];
      *(float4*)(W1s + row*132 + c4*4) = v;
    }
  }
  if (t < BB) h[t] = 0;
  if (t < DD){
    g_acc[b*DD + t] = 0.f;
    float v = embs[(size_t)b*NN*DD + t];
    tgp[(t >> 5)*33 + (t & 31)] = v;
  }
  for (int i = t; i < NN-1; i += 512) sb[i] = bidx[b*NN + 1 + i];
  __syncthreads();

  {
    int d = t >> 2, kq = t & 3;
    const float* w = W1s + d*132 + kq*32;
    const float* tq = tgp + kq*33;
    float s = 0.f;
    #pragma unroll
    for (int k = 0; k < 32; k++) s += w[k]*tq[k];
    s += __shfl_xor_sync(0xffffffffu, s, 1);
    s += __shfl_xor_sync(0xffffffffu, s, 2);
    if (kq == 0) g_T[b*DD + d] = s + b1[d];
  }

  for (int i = t; i < NN-1; i += 512)
    atomicAdd(&h[sb[i]], 1);
  __syncthreads();

  int lane = t & 31, wrp = t >> 5;
  int v = 0, x = 0;
  if (t < BB){ v = h[t]; g_histT[t*BB + b] = v; }
  x = v;
  #pragma unroll
  for (int o = 1; o < 32; o <<= 1){
    int y = __shfl_up_sync(0xffffffffu, x, o);
    if (lane >= o) x += y;
  }
  if (t < BB && lane == 31) wsum[wrp] = x;
  __syncthreads();
  if (t < 32){
    int s = (t < 8) ? wsum[t] : 0;
    #pragma unroll
    for (int o = 1; o < 8; o <<= 1){
      int y = __shfl_up_sync(0xffffffffu, s, o);
      if (t >= o) s += y;
    }
    if (t < 8) wsum[t] = s;
  }
  __syncthreads();
  if (t < BB){
    int off = (wrp > 0) ? wsum[wrp-1] : 0;
    h[t] = off + x - v;
  }
  __syncthreads();
  for (int i = t; i < NN-1; i += 512){
    int s = sb[i];
    int pos = atomicAdd(&h[s], 1);
    g_perm[b*RPB + pos] = ((1 + i) << 8) | s;
  }
  if (t == 0) g_perm[b*RPB + NN-1] = (int)(0x80000000u | (1u << 8));
}

// ---------------- main: warp-autonomous 32-row slices (B-fragment reuse) ----------------
__global__ void __launch_bounds__(256, 1) k_main(const float* __restrict__ embs,
                                                 const float* __restrict__ W1){
  extern __shared__ char sm[];
  uint32_t sbase = smem_u32(sm);
  const uint32_t Wb = sbase;

  int tid = threadIdx.x;
  int lane = tid & 31, w = tid >> 5;

  const uint32_t Eb = sbase + 32768 + (uint32_t)w*8448;   // E 8KB; D overlays first 4224B
  float* Dw = (float*)(sm + 32768 + w*8448);

  // ---- W1b -> smem fp16 once ----
  {
    int d = tid >> 1, hh = tid & 1;
    const float4* wr = (const float4*)(W1 + (size_t)d*2*DD + DD + hh*64);
    uint32_t sw = (uint32_t)(d & 7) << 4;
    char* dst = sm + d*256;
    #pragma unroll
    for (int i = 0; i < 8; i++){
      float4 v0 = wr[2*i], v1 = wr[2*i+1];
      uint4 q;
      q.x = h2u(__floats2half2_rn(v0.x, v0.y));
      q.y = h2u(__floats2half2_rn(v0.z, v0.w));
      q.z = h2u(__floats2half2_rn(v1.x, v1.y));
      q.w = h2u(__floats2half2_rn(v1.z, v1.w));
      *(uint4*)(dst + (((uint32_t)(hh*128 + i*16)) ^ sw)) = q;
    }
  }
  __syncthreads();   // only block barrier

  const uint32_t ln15 = lane & 15;
  const uint32_t sxor = (uint32_t)(lane & 7) << 4;
  const uint32_t kbl  = (uint32_t)(lane >> 4) << 4;
  const uint32_t baseA0 = Eb + ln15*256;
  const uint32_t baseA1 = Eb + (16u + ln15)*256;
  const uint32_t baseB = Wb + ln15*256;

  const int r2 = lane >> 1, eh = lane & 1;
  const uint32_t esw0 = (uint32_t)(r2 & 7) << 4;

  for (int slice = blockIdx.x*8 + w; slice < SLICES32; slice += WSTRIDE){
    int batch = slice >> 6;
    int rowbase = batch*RPB + (slice & 63)*32;

    // ---- gather 32 rows (two 16-row groups) -> fp16 swizzled E ----
    int pv0, pv1;
    #pragma unroll
    for (int s2 = 0; s2 < 2; s2++){
      int pv = g_perm[rowbase + s2*16 + r2];
      if (s2 == 0) pv0 = pv; else pv1 = pv;
      int node = (pv >> 8) & 2047;
      const float4* src = (const float4*)(embs + ((size_t)batch*NN + node)*DD + eh*64);
      char* edst = (char*)sm + 32768 + w*8448 + (s2*16 + r2)*256;
      #pragma unroll
      for (int half = 0; half < 2; half++){
        float4 vv[8];
        #pragma unroll
        for (int i = 0; i < 8; i++) vv[i] = src[half*8 + i];
        #pragma unroll
        for (int i = 0; i < 4; i++){
          uint4 q;
          q.x = h2u(__floats2half2_rn(vv[2*i].x, vv[2*i].y));
          q.y = h2u(__floats2half2_rn(vv[2*i].z, vv[2*i].w));
          q.z = h2u(__floats2half2_rn(vv[2*i+1].x, vv[2*i+1].y));
          q.w = h2u(__floats2half2_rn(vv[2*i+1].z, vv[2*i+1].w));
          *(uint4*)(edst + (((uint32_t)(eh*128 + half*64 + i*16)) ^ esw0)) = q;
        }
      }
    }
    __syncwarp();

    // ---- MMA: 32 rows x 128 cols, K=128; B fragments shared across row groups ----
    float acc0[16][4], acc1[16][4];
    #pragma unroll
    for (int i = 0; i < 16; i++){
      acc0[i][0]=0.f; acc0[i][1]=0.f; acc0[i][2]=0.f; acc0[i][3]=0.f;
      acc1[i][0]=0.f; acc1[i][1]=0.f; acc1[i][2]=0.f; acc1[i][3]=0.f;
    }
    #pragma unroll
    for (int k0 = 0; k0 < 8; k0++){
      uint32_t ko = (((uint32_t)k0 << 5) | kbl) ^ sxor;
      uint32_t a0, a1, a2, a3, a4, a5, a6, a7;
      ldsm4(a0, a1, a2, a3, baseA0 + ko);
      ldsm4(a4, a5, a6, a7, baseA1 + ko);
      uint32_t bad = baseB + ko;
      #pragma unroll
      for (int j = 0; j < 8; j++){
        uint32_t b0, b1, b2, b3;
        ldsm4(b0, b1, b2, b3, bad);
        bad += 16*256;
        mma16816(acc0[2*j],   a0, a1, a2, a3, b0, b2);
        mma16816(acc0[2*j+1], a0, a1, a2, a3, b1, b3);
        mma16816(acc1[2*j],   a4, a5, a6, a7, b0, b2);
        mma16816(acc1[2*j+1], a4, a5, a6, a7, b1, b3);
      }
    }
    __syncwarp();   // all E consumed; D may overwrite buffer

    // ---- epilogue: two 16-row groups, each via two 8-row D passes ----
    float tv[4];
    #pragma unroll
    for (int j = 0; j < 4; j++) tv[j] = g_T[batch*DD + lane + 32*j];

    int r0 = lane >> 2;
    int c0 = 2*(lane & 3);
    int cur = -1;
    float run[4] = {0.f, 0.f, 0.f, 0.f};

    #pragma unroll
    for (int s2 = 0; s2 < 2; s2++){
      int pv = (s2 == 0) ? pv0 : pv1;
      // rows 0-7 of group
      #pragma unroll
      for (int nt = 0; nt < 16; nt++){
        float2 v = (s2 == 0) ? make_float2(acc0[nt][0], acc0[nt][1])
                             : make_float2(acc1[nt][0], acc1[nt][1]);
        *(float2*)(Dw + r0*132 + c0 + nt*8) = v;
      }
      __syncwarp();
      #pragma unroll
      for (int r = 0; r < 8; r++){
        int pvr = __shfl_sync(0xffffffffu, pv, 2*r);
        int s = (pvr < 0) ? -1 : (pvr & 255);
        if (s != cur){
          if (cur >= 0){
            #pragma unroll
            for (int j = 0; j < 4; j++) atomicAdd(&g_acc[cur*DD + lane + 32*j], run[j]);
          }
          run[0]=run[1]=run[2]=run[3]=0.f;
          cur = s;
        }
        if (s >= 0){
          #pragma unroll
          for (int j = 0; j < 4; j++)
            run[j] += fmaxf(Dw[r*132 + lane + 32*j] + tv[j], 0.f);
        }
      }
      __syncwarp();
      // rows 8-15 of group
      #pragma unroll
      for (int nt = 0; nt < 16; nt++){
        float2 v = (s2 == 0) ? make_float2(acc0[nt][2], acc0[nt][3])
                             : make_float2(acc1[nt][2], acc1[nt][3]);
        *(float2*)(Dw + r0*132 + c0 + nt*8) = v;
      }
      __syncwarp();
      #pragma unroll
      for (int r = 0; r < 8; r++){
        int pvr = __shfl_sync(0xffffffffu, pv, 2*(r + 8));
        int s = (pvr < 0) ? -1 : (pvr & 255);
        if (s != cur){
          if (cur >= 0){
            #pragma unroll
            for (int j = 0; j < 4; j++) atomicAdd(&g_acc[cur*DD + lane + 32*j], run[j]);
          }
          run[0]=run[1]=run[2]=run[3]=0.f;
          cur = s;
        }
        if (s >= 0){
          #pragma unroll
          for (int j = 0; j < 4; j++)
            run[j] += fmaxf(Dw[r*132 + lane + 32*j] + tv[j], 0.f);
        }
      }
      __syncwarp();
    }
    if (cur >= 0){
      #pragma unroll
      for (int j = 0; j < 4; j++) atomicAdd(&g_acc[cur*DD + lane + 32*j], run[j]);
    }
    __syncwarp();   // D reads done before next slice's E write
  }
}

// ---------------- final ----------------
__global__ void __launch_bounds__(256) k_final(const float* __restrict__ W2,
                                               const float* __restrict__ b2,
                                               float* __restrict__ out){
  __shared__ float arow[DD];
  __shared__ int wsum[8];
  int s = blockIdx.x, t = threadIdx.x;
  int lane = t & 31, wrp = t >> 5;

  if (t < DD) arow[t] = g_acc[s*DD + t];
  int c = g_histT[s*BB + t];
  #pragma unroll
  for (int o = 16; o > 0; o >>= 1) c += __shfl_xor_sync(0xffffffffu, c, o);
  if (lane == 0) wsum[wrp] = c;
  __syncthreads();
  int cnt = wsum[0] + wsum[1] + wsum[2] + wsum[3] + wsum[4] + wsum[5] + wsum[6] + wsum[7];

  int d = t >> 1, half = t & 1;
  const float* ww = W2 + (size_t)d*DD + half*64;
  const float* ar = arow + half*64;
  float r = 0.f;
  #pragma unroll
  for (int j = 0; j < 64; j++) r += ww[j]*ar[j];
  r += __shfl_xor_sync(0xffffffffu, r, 1);
  if (half == 0) out[s*DD + d] = r + b2[d]*(float)cnt;
}

// ---------------- launch ----------------
extern "C" void kernel_launch(void* const* d_in, const int* in_sizes, int n_in,
                              void* d_out, int out_size){
  const float* embs = (const float*)d_in[0];
  const float* W1   = (const float*)d_in[1];
  const float* b1   = (const float*)d_in[2];
  const float* W2   = (const float*)d_in[3];
  const float* b2   = (const float*)d_in[4];
  const int*   bidx = (const int*)d_in[5];
  float* out = (float*)d_out;

  cudaFuncSetAttribute(k_prep, cudaFuncAttributeMaxDynamicSharedMemorySize, SMEM_PREP);
  cudaFuncSetAttribute(k_main, cudaFuncAttributeMaxDynamicSharedMemorySize, SMEM_MAIN);

  k_prep <<<BB, 512, SMEM_PREP>>>(bidx, embs, W1, b1);
  k_main <<<GRID_MAIN, 256, SMEM_MAIN>>>(embs, W1);
  k_final<<<BB, 256>>>(W2, b2, out);
}